// round 14
// baseline (speedup 1.0000x reference)
#include <cuda_runtime.h>
#include <math.h>

#define BB 4096
#define TT 750
#define WIN 11
#define NSN (TT * WIN)          // 8250
#define NCHUNK 256              // row chunks (16 rows each)
#define CROWS 16
#define TILE_T 250              // t-columns per tile (3 tiles = 750)
#define NOUT (TT * 6)           // 4500 S_d[t] outputs
#define A_GRID (NCHUNK * 3)     // 768
#define MAIN_GRID 512
#define NS_SKIP_THRESH 176.0f   // exp(-88): contribution negligible vs loss ~12.5

// Scratch (static device globals; no allocation allowed)
__device__ float g_part[(size_t)NCHUNK * NOUT];     // [z][o], 4.6 MB, o = t*6+(d-1)
__device__ float g_edge_part[31 * NCHUNK];          // [e][z]
__device__ float g_apart[A_GRID];                   // per-A-block sum of (a-a2)^2
__device__ float g_ns[NSN];
__device__ unsigned int g_mask[TT];                 // bits w != 6 only
__device__ unsigned int g_any;                      // OR of all masks
__device__ float g_bpart[MAIN_GRID];
__device__ unsigned int g_done;                     // zero-init; last block resets

// ---------------------------------------------------------------------------
// Kernel A: S_d partials (d=1..6) + FUSED term-2 partial sum.
// Block = (chunk z of 16 rows) x (t-tile of 250 cols).
// ALL 32 global loads (16 a + 16 a2) are issued into register arrays first
// (launch_bounds(256,4) -> <=64 regs -> MLP=32, ONE DRAM round), then a is
// STS'd to the 16x256 halo tile. Thread's own column value stays in va[] so
// 'at' and the diff^2 sum never touch smem; only the 6 neighbors are LDS.
// Partials stored TRANSPOSED [z][o]: 6 consecutive floats/thread (coalesced).
// Edge (scrambled-pad) partials per reference tile-reshape:
//   front(b,j)=a[(6b+j)%B,0]; back(b,j)=a[(6b+j-755)%B,T-1].
// ---------------------------------------------------------------------------
__global__ __launch_bounds__(256, 4) void k_ns_part(const float* __restrict__ a,
                                                     const float* __restrict__ a2) {
    __shared__ float s[CROWS][256];
    const int tile = blockIdx.x % 3;
    const int z    = blockIdx.x / 3;
    const int t0   = tile * TILE_T;
    const int b0   = z * CROWS;
    const int tid  = threadIdx.x;

    const int gc = t0 + tid;
    const bool cv = (gc < TT);
    const bool act = (tid < TILE_T);

    // Issue all 32 independent loads (one DRAM round, MLP=32)
    float va[CROWS], v2[CROWS];
    {
        const float* __restrict__ pa  = a  + gc;
        const float* __restrict__ pa2 = a2 + gc;
#pragma unroll
        for (int r = 0; r < CROWS; r++)
            va[r] = cv ? pa[(size_t)(b0 + r) * TT] : 0.0f;
#pragma unroll
        for (int r = 0; r < CROWS; r++)
            v2[r] = cv ? pa2[(size_t)(b0 + r) * TT] : 0.0f;
    }
#pragma unroll
    for (int r = 0; r < CROWS; r++) s[r][tid] = va[r];
    __syncthreads();

    // Column-stationary S accumulation (6 LDS/r) + register-only diff^2
    float S[6] = {0.f, 0.f, 0.f, 0.f, 0.f, 0.f};
    float acc2 = 0.0f;
    if (act) {
#pragma unroll 8
        for (int r = 0; r < CROWS; r++) {
            const float at = va[r];
#pragma unroll
            for (int d = 1; d <= 6; d++) {
                const float df = at - s[r][tid + d];
                S[d - 1] += df * df;
            }
            const float dd = at - v2[r];
            acc2 += dd * dd;
        }
    }

    // Edge partials
    if (tile == 0 && tid < 21) {
        int et = 0, ew = 0, acc = 0;
        for (int t = 0; t < 6; t++) {
            const int c = 6 - t;
            if (tid < acc + c) { et = t; ew = tid - acc; break; }
            acc += c;
        }
        const int j = et + ew;          // j < 6
        float eacc = 0.0f;
        for (int r0 = 0; r0 < CROWS; r0 += 8) {
            float pv[8];
#pragma unroll
            for (int k = 0; k < 8; k++)
                pv[k] = __ldg(a + (size_t)((6 * (b0 + r0 + k) + j) & (BB - 1)) * TT);
#pragma unroll
            for (int k = 0; k < 8; k++) {
                const float d = s[r0 + k][et] - pv[k];
                eacc += d * d;
            }
        }
        g_edge_part[tid * NCHUNK + z] = eacc;
    } else if (tile == 2 && tid < 10) {
        int et = 0, ew = 0, acc = 0;
        for (int t = 746; t < 750; t++) {
            const int c = t - 745;
            if (tid < acc + c) { et = t; ew = (756 - t) + (tid - acc); break; }
            acc += c;
        }
        const int j = et + ew;          // j >= 756
        const int col = et - t0;        // 246..249
        float eacc = 0.0f;
        for (int r0 = 0; r0 < CROWS; r0 += 8) {
            float pv[8];
#pragma unroll
            for (int k = 0; k < 8; k++)
                pv[k] = __ldg(a + (size_t)((6 * (b0 + r0 + k) + (j - 755)) & (BB - 1)) * TT + (TT - 1));
#pragma unroll
            for (int k = 0; k < 8; k++) {
                const float d = s[r0 + k][col] - pv[k];
                eacc += d * d;
            }
        }
        g_edge_part[(21 + tid) * NCHUNK + z] = eacc;
    }

    // Coalesced transposed S store
    if (act) {
        const int t = t0 + tid;
        float* __restrict__ p = g_part + (size_t)z * NOUT + t * 6;
#pragma unroll
        for (int d = 0; d < 6; d++) p[d] = S[d];
    }

    // Block-reduce diff^2 partial (fixed order within block -> deterministic)
    const int lane = tid & 31, warp = tid >> 5;
#pragma unroll
    for (int off = 16; off; off >>= 1) acc2 += __shfl_down_sync(0xffffffffu, acc2, off);
    __shared__ float sw[8];
    if (lane == 0) sw[warp] = acc2;
    __syncthreads();
    if (tid == 0) {
        float bs = 0.0f;
#pragma unroll
        for (int k = 0; k < 8; k++) bs += sw[k];
        g_apart[blockIdx.x] = bs;
    }
}

// ---------------------------------------------------------------------------
// Kernel R: reduce partials over z -> g_ns[t][11] + per-t mask + g_any.
// 21 blocks x 512 threads; the 252 outputs per block (36 t + 6-t halo, x6 d)
// are each summed by TWO threads (z halves) to halve the dependent-load chain.
// Mask EXCLUDES w=6: that term is identically zero (j=t+6 always interior, so
// d2 == |a2[i,t]-a2[i,t]| == 0 for any input). Fixed-order -> deterministic.
// ---------------------------------------------------------------------------
__global__ __launch_bounds__(512) void k_reduce_mask() {
    const int t0 = blockIdx.x * 36;
    const int o0 = t0 * 6 - 36;
    const int tid = threadIdx.x, lane = tid & 31, warp = tid >> 5;
    const int half = tid >> 8;          // 0 or 1
    const int ol = tid & 255;
    __shared__ float sSh[2][256];
    __shared__ float sE[31];

    float acc = 0.0f;
    const int o = o0 + ol;
    if (ol < 252 && o >= 0 && o < NOUT) {
        const float* __restrict__ p = g_part + o + (size_t)half * 128 * NOUT;
#pragma unroll 8
        for (int zz = 0; zz < 128; zz++) acc += p[(size_t)zz * NOUT];
    }
    sSh[half][ol] = acc;

    // Edge sums (blocks 0 and 20); warp-per-e, coalesced over z
    if (blockIdx.x == 0) {
        for (int e = warp; e < 21; e += 16) {
            const float* __restrict__ p = g_edge_part + (size_t)e * NCHUNK;
            float v = 0.0f;
#pragma unroll
            for (int k = 0; k < 8; k++) v += p[lane + 32 * k];
#pragma unroll
            for (int off = 16; off; off >>= 1) v += __shfl_down_sync(0xffffffffu, v, off);
            if (lane == 0) sE[e] = v;
        }
    } else if (blockIdx.x == 20) {
        for (int e = 21 + warp; e < 31; e += 16) {
            const float* __restrict__ p = g_edge_part + (size_t)e * NCHUNK;
            float v = 0.0f;
#pragma unroll
            for (int k = 0; k < 8; k++) v += p[lane + 32 * k];
#pragma unroll
            for (int off = 16; off; off >>= 1) v += __shfl_down_sync(0xffffffffu, v, off);
            if (lane == 0) sE[e] = v;
        }
    }
    __syncthreads();

    if (tid < 36) {
        const int t = t0 + tid;
        if (t < TT) {
            unsigned m = 0;
#pragma unroll
            for (int w = 0; w < WIN; w++) {
                float v;
                if (w == 6) {
                    v = 0.0f;
                } else if (w > 6) {                     // d = w-6, S_d[t]
                    const int x = (t * 6 + (w - 6) - 1) - o0;
                    if (t + w < 756) v = sSh[0][x] + sSh[1][x];
                    else             v = sE[21 + (t - 746) * (t - 745) / 2 + (w - (756 - t))];
                } else {                                // d = 6-w, S_d[t-d]
                    const int d = 6 - w;
                    const int x = ((t - d) * 6 + d - 1) - o0;
                    if (t - d >= 0) v = sSh[0][x] + sSh[1][x];
                    else            v = sE[t * (13 - t) / 2 + w];
                }
                g_ns[t * WIN + w] = v;
                if (w != 6 && v <= NS_SKIP_THRESH) m |= (1u << w);
            }
            g_mask[t] = m;
            if (m) atomicOr(&g_any, m);
        }
    }
}

// ---------------------------------------------------------------------------
// Kernel M: term1 (only when g_any != 0; faithful warp-per-row path) + fused
// final reduction. term2 partials already live in g_apart (from kernel A).
// Fast path (g_any==0, provable common case): zero memory work per block.
// Final (last block, fixed order): out = (sum bpart + 0.1*sum apart)/B.
// ---------------------------------------------------------------------------
__global__ __launch_bounds__(256) void k_main(const float* __restrict__ a,
                                              const float* __restrict__ a2,
                                              float* __restrict__ out) {
    const int tid = threadIdx.x, lane = tid & 31, warp = tid >> 5;

    float acc1 = 0.0f;
    if (__ldg(&g_any) != 0u) {
        const int i = blockIdx.x * 8 + warp;
        const float* __restrict__ ra  = a  + (size_t)i * TT;
        const float* __restrict__ ra2 = a2 + (size_t)i * TT;
        for (int t = lane; t < TT; t += 32) {
            const float a2v = ra2[t];
            unsigned m = g_mask[t];
            while (m) {
                const int w = __ffs(m) - 1;
                m &= m - 1;
                const int j = t + w;
                float a3w;
                if (j < 6)            a3w = a2[(size_t)((6 * i + j) & (BB - 1)) * TT];
                else if (j < TT + 6)  a3w = ra2[j - 6];
                else                  a3w = a2[(size_t)((6 * i + (j - 755)) & (BB - 1)) * TT + (TT - 1)];
                const float d2 = fabsf(a2v - a3w);
                if (d2 != 0.0f) {
                    float mx = -3.0e38f;
#pragma unroll
                    for (int w2 = 0; w2 < WIN; w2++) {
                        const int j2 = t + w2;
                        float a4w;
                        if (j2 < 6)           a4w = a[(size_t)((6 * i + j2) & (BB - 1)) * TT];
                        else if (j2 < TT + 6) a4w = ra[j2 - 6];
                        else                  a4w = a[(size_t)((6 * i + (j2 - 755)) & (BB - 1)) * TT + (TT - 1)];
                        const float tv = a[(size_t)((11 * i + w2) & (BB - 1)) * TT + t];
                        mx = fmaxf(mx, tv - a4w);
                    }
                    const float g = mx * mx;             // E_G = 1
                    const float ns = g_ns[t * WIN + w];
                    const float expo = fmaxf(ns, g);     // relu(ns-g)+g
                    acc1 += __expf(-0.5f * expo) * d2;   // SIGMA = 1
                }
            }
        }
    }

#pragma unroll
    for (int off = 16; off; off >>= 1) acc1 += __shfl_down_sync(0xffffffffu, acc1, off);

    __shared__ float sw[8];
    __shared__ bool s_last;
    if (lane == 0) sw[warp] = acc1;
    __syncthreads();
    if (tid == 0) {
        float bs = 0.0f;
#pragma unroll
        for (int k = 0; k < 8; k++) bs += sw[k];
        g_bpart[blockIdx.x] = bs;
        __threadfence();
        s_last = (atomicAdd(&g_done, 1u) == (unsigned)(gridDim.x - 1));
    }
    __syncthreads();

    if (s_last) {
        __shared__ double dred[256];
        double s = (double)g_bpart[tid] + (double)g_bpart[tid + 256];
        s += 0.1 * ((double)g_apart[tid] + (double)g_apart[tid + 256] +
                    (double)g_apart[tid + 512]);        // E_THETA = 0.1
        dred[tid] = s;
        __syncthreads();
        for (int st = 128; st; st >>= 1) {
            if (tid < st) dred[tid] += dred[tid + st];
            __syncthreads();
        }
        if (tid == 0) {
            out[0] = (float)(dred[0] / (double)BB);      // E_ALPHA = 1
            g_any = 0u;                                  // all blocks already read it
            g_done = 0u;                                 // reset for graph replay
        }
    }
}

// ---------------------------------------------------------------------------
extern "C" void kernel_launch(void* const* d_in, const int* in_sizes, int n_in,
                              void* d_out, int out_size) {
    (void)in_sizes; (void)n_in; (void)out_size;
    const float* a  = (const float*)d_in[0];   // actioness   [4096,750]
    const float* a2 = (const float*)d_in[1];   // actioness_2 [4096,750]
    float* out = (float*)d_out;

    k_ns_part<<<A_GRID, 256>>>(a, a2);
    k_reduce_mask<<<21, 512>>>();
    k_main<<<MAIN_GRID, 256>>>(a, a2, out);
}

// round 17
// speedup vs baseline: 1.0986x; 1.0986x over previous
#include <cuda_runtime.h>
#include <math.h>

#define BB 4096
#define TT 750
#define WIN 11
#define NSN (TT * WIN)          // 8250
#define NCHUNK 256              // row chunks (16 rows each)
#define CROWS 16
#define TILE_T 250              // t-columns per tile (3 tiles = 750)
#define NOUT (TT * 6)           // 4500 S_d[t] outputs
#define A_GRID (NCHUNK * 3)     // 768
#define MAIN_GRID 512
#define NS_SKIP_THRESH 176.0f   // exp(-88): contribution negligible vs loss ~12.5

// Scratch (static device globals; no allocation allowed)
__device__ float g_part[(size_t)NCHUNK * NOUT];     // [z][o], 4.6 MB, o = t*6+(d-1)
__device__ float g_edge_part[31 * NCHUNK];          // [e][z]
__device__ float g_apart[A_GRID];                   // per-A-block sum of (a-a2)^2
__device__ float g_ns[NSN];
__device__ unsigned int g_mask[TT];                 // bits w != 6 only
__device__ unsigned int g_any;                      // OR of all masks
__device__ float g_bpart[MAIN_GRID];
__device__ unsigned int g_done;                     // zero-init; last block resets

// ---------------------------------------------------------------------------
// Kernel A: S_d partials (d=1..6) + FUSED term-2 partial sum.
// Block = (chunk z of 16 rows) x (t-tile of 250 cols, staged 256 w/ halo).
// float2 loads (rows are 3000B -> every row start + tile offset (0/1000/2000B)
// is 8B-aligned): 8 LDG.64 for a + 8 for a2 per thread (16 total vs 32
// scalar), STS.64 into the 16x256 halo tile; diff^2 computed straight from
// load registers with the c2<125 guard reproducing the exact 250-col
// partition (halo cols not double-counted).
// Compute phase: column-stationary, 7 LDS + 6 FFMA per row.
// Partials stored TRANSPOSED [z][o]: 6 consecutive floats/thread (coalesced).
// Edge (scrambled-pad) partials per reference tile-reshape:
//   front(b,j)=a[(6b+j)%B,0]; back(b,j)=a[(6b+j-755)%B,T-1].
// ---------------------------------------------------------------------------
__global__ __launch_bounds__(256, 4) void k_ns_part(const float* __restrict__ a,
                                                     const float* __restrict__ a2) {
    __shared__ float s[CROWS][256];
    const int tile = blockIdx.x % 3;
    const int z    = blockIdx.x / 3;
    const int t0   = tile * TILE_T;
    const int b0   = z * CROWS;
    const int tid  = threadIdx.x;

    // Issue 16 float2 loads (covers the 16x256 tile incl. 6-col halo)
    float2 va[8], v2[8];
#pragma unroll
    for (int k = 0; k < 8; k++) {
        const int idx = k * 256 + tid;
        const int r = idx >> 7, c2 = idx & 127;
        const int gc = t0 + 2 * c2;                 // even; 750 even -> pair in-bounds
        va[k] = (gc < TT) ? *(const float2*)(a + (size_t)(b0 + r) * TT + gc)
                          : make_float2(0.f, 0.f);
    }
#pragma unroll
    for (int k = 0; k < 8; k++) {
        const int idx = k * 256 + tid;
        const int r = idx >> 7, c2 = idx & 127;
        const int gc = t0 + 2 * c2;
        v2[k] = (gc < TT) ? *(const float2*)(a2 + (size_t)(b0 + r) * TT + gc)
                          : make_float2(0.f, 0.f);
    }

    // STS + register-only diff^2 (cols t0..t0+249 exactly: c2 < 125)
    float acc2 = 0.0f;
#pragma unroll
    for (int k = 0; k < 8; k++) {
        const int idx = k * 256 + tid;
        const int r = idx >> 7, c2 = idx & 127;
        *(float2*)&s[r][2 * c2] = va[k];
        if (c2 < 125) {
            const float d0 = va[k].x - v2[k].x;
            const float d1 = va[k].y - v2[k].y;
            acc2 += d0 * d0 + d1 * d1;
        }
    }
    __syncthreads();

    // Column-stationary S accumulation
    float S[6] = {0.f, 0.f, 0.f, 0.f, 0.f, 0.f};
    const bool act = (tid < TILE_T);
    if (act) {
#pragma unroll 8
        for (int r = 0; r < CROWS; r++) {
            const float at = s[r][tid];
#pragma unroll
            for (int d = 1; d <= 6; d++) {
                const float df = at - s[r][tid + d];
                S[d - 1] += df * df;
            }
        }
    }

    // Edge partials
    if (tile == 0 && tid < 21) {
        int et = 0, ew = 0, acc = 0;
        for (int t = 0; t < 6; t++) {
            const int c = 6 - t;
            if (tid < acc + c) { et = t; ew = tid - acc; break; }
            acc += c;
        }
        const int j = et + ew;          // j < 6
        float eacc = 0.0f;
        for (int r0 = 0; r0 < CROWS; r0 += 8) {
            float pv[8];
#pragma unroll
            for (int k = 0; k < 8; k++)
                pv[k] = __ldg(a + (size_t)((6 * (b0 + r0 + k) + j) & (BB - 1)) * TT);
#pragma unroll
            for (int k = 0; k < 8; k++) {
                const float d = s[r0 + k][et] - pv[k];
                eacc += d * d;
            }
        }
        g_edge_part[tid * NCHUNK + z] = eacc;
    } else if (tile == 2 && tid < 10) {
        int et = 0, ew = 0, acc = 0;
        for (int t = 746; t < 750; t++) {
            const int c = t - 745;
            if (tid < acc + c) { et = t; ew = (756 - t) + (tid - acc); break; }
            acc += c;
        }
        const int j = et + ew;          // j >= 756
        const int col = et - t0;        // 246..249
        float eacc = 0.0f;
        for (int r0 = 0; r0 < CROWS; r0 += 8) {
            float pv[8];
#pragma unroll
            for (int k = 0; k < 8; k++)
                pv[k] = __ldg(a + (size_t)((6 * (b0 + r0 + k) + (j - 755)) & (BB - 1)) * TT + (TT - 1));
#pragma unroll
            for (int k = 0; k < 8; k++) {
                const float d = s[r0 + k][col] - pv[k];
                eacc += d * d;
            }
        }
        g_edge_part[(21 + tid) * NCHUNK + z] = eacc;
    }

    // Coalesced transposed S store
    if (act) {
        const int t = t0 + tid;
        float* __restrict__ p = g_part + (size_t)z * NOUT + t * 6;
#pragma unroll
        for (int d = 0; d < 6; d++) p[d] = S[d];
    }

    // Block-reduce diff^2 partial (fixed order -> deterministic)
    const int lane = tid & 31, warp = tid >> 5;
#pragma unroll
    for (int off = 16; off; off >>= 1) acc2 += __shfl_down_sync(0xffffffffu, acc2, off);
    __shared__ float sw[8];
    if (lane == 0) sw[warp] = acc2;
    __syncthreads();
    if (tid == 0) {
        float bs = 0.0f;
#pragma unroll
        for (int k = 0; k < 8; k++) bs += sw[k];
        g_apart[blockIdx.x] = bs;
    }
}

// ---------------------------------------------------------------------------
// Kernel R: reduce partials over z -> g_ns[t][11] + per-t mask + g_any.
// 21 blocks x 512 threads; the 252 outputs per block (36 t + 6-t halo, x6 d)
// are each summed by TWO threads (z halves) to halve the dependent-load chain.
// Mask EXCLUDES w=6: that term is identically zero (j=t+6 always interior, so
// d2 == |a2[i,t]-a2[i,t]| == 0 for any input). Fixed-order -> deterministic.
// ---------------------------------------------------------------------------
__global__ __launch_bounds__(512) void k_reduce_mask() {
    const int t0 = blockIdx.x * 36;
    const int o0 = t0 * 6 - 36;
    const int tid = threadIdx.x, lane = tid & 31, warp = tid >> 5;
    const int half = tid >> 8;          // 0 or 1
    const int ol = tid & 255;
    __shared__ float sSh[2][256];
    __shared__ float sE[31];

    float acc = 0.0f;
    const int o = o0 + ol;
    if (ol < 252 && o >= 0 && o < NOUT) {
        const float* __restrict__ p = g_part + o + (size_t)half * 128 * NOUT;
#pragma unroll 8
        for (int zz = 0; zz < 128; zz++) acc += p[(size_t)zz * NOUT];
    }
    sSh[half][ol] = acc;

    // Edge sums (blocks 0 and 20); warp-per-e, coalesced over z
    if (blockIdx.x == 0) {
        for (int e = warp; e < 21; e += 16) {
            const float* __restrict__ p = g_edge_part + (size_t)e * NCHUNK;
            float v = 0.0f;
#pragma unroll
            for (int k = 0; k < 8; k++) v += p[lane + 32 * k];
#pragma unroll
            for (int off = 16; off; off >>= 1) v += __shfl_down_sync(0xffffffffu, v, off);
            if (lane == 0) sE[e] = v;
        }
    } else if (blockIdx.x == 20) {
        for (int e = 21 + warp; e < 31; e += 16) {
            const float* __restrict__ p = g_edge_part + (size_t)e * NCHUNK;
            float v = 0.0f;
#pragma unroll
            for (int k = 0; k < 8; k++) v += p[lane + 32 * k];
#pragma unroll
            for (int off = 16; off; off >>= 1) v += __shfl_down_sync(0xffffffffu, v, off);
            if (lane == 0) sE[e] = v;
        }
    }
    __syncthreads();

    if (tid < 36) {
        const int t = t0 + tid;
        if (t < TT) {
            unsigned m = 0;
#pragma unroll
            for (int w = 0; w < WIN; w++) {
                float v;
                if (w == 6) {
                    v = 0.0f;
                } else if (w > 6) {                     // d = w-6, S_d[t]
                    const int x = (t * 6 + (w - 6) - 1) - o0;
                    if (t + w < 756) v = sSh[0][x] + sSh[1][x];
                    else             v = sE[21 + (t - 746) * (t - 745) / 2 + (w - (756 - t))];
                } else {                                // d = 6-w, S_d[t-d]
                    const int d = 6 - w;
                    const int x = ((t - d) * 6 + d - 1) - o0;
                    if (t - d >= 0) v = sSh[0][x] + sSh[1][x];
                    else            v = sE[t * (13 - t) / 2 + w];
                }
                g_ns[t * WIN + w] = v;
                if (w != 6 && v <= NS_SKIP_THRESH) m |= (1u << w);
            }
            g_mask[t] = m;
            if (m) atomicOr(&g_any, m);
        }
    }
}

// ---------------------------------------------------------------------------
// Kernel M: term1 (only when g_any != 0; faithful warp-per-row path) + fused
// final reduction. term2 partials already live in g_apart (from kernel A).
// Fast path (g_any==0, provable common case): zero memory work per block.
// Final (last block, fixed order): out = (sum bpart + 0.1*sum apart)/B.
// ---------------------------------------------------------------------------
__global__ __launch_bounds__(256) void k_main(const float* __restrict__ a,
                                              const float* __restrict__ a2,
                                              float* __restrict__ out) {
    const int tid = threadIdx.x, lane = tid & 31, warp = tid >> 5;

    float acc1 = 0.0f;
    if (g_any != 0u) {
        const int i = blockIdx.x * 8 + warp;
        const float* __restrict__ ra  = a  + (size_t)i * TT;
        const float* __restrict__ ra2 = a2 + (size_t)i * TT;
        for (int t = lane; t < TT; t += 32) {
            const float a2v = ra2[t];
            unsigned m = g_mask[t];
            while (m) {
                const int w = __ffs(m) - 1;
                m &= m - 1;
                const int j = t + w;
                float a3w;
                if (j < 6)            a3w = a2[(size_t)((6 * i + j) & (BB - 1)) * TT];
                else if (j < TT + 6)  a3w = ra2[j - 6];
                else                  a3w = a2[(size_t)((6 * i + (j - 755)) & (BB - 1)) * TT + (TT - 1)];
                const float d2 = fabsf(a2v - a3w);
                if (d2 != 0.0f) {
                    float mx = -3.0e38f;
#pragma unroll
                    for (int w2 = 0; w2 < WIN; w2++) {
                        const int j2 = t + w2;
                        float a4w;
                        if (j2 < 6)           a4w = a[(size_t)((6 * i + j2) & (BB - 1)) * TT];
                        else if (j2 < TT + 6) a4w = ra[j2 - 6];
                        else                  a4w = a[(size_t)((6 * i + (j2 - 755)) & (BB - 1)) * TT + (TT - 1)];
                        const float tv = a[(size_t)((11 * i + w2) & (BB - 1)) * TT + t];
                        mx = fmaxf(mx, tv - a4w);
                    }
                    const float g = mx * mx;             // E_G = 1
                    const float ns = g_ns[t * WIN + w];
                    const float expo = fmaxf(ns, g);     // relu(ns-g)+g
                    acc1 += __expf(-0.5f * expo) * d2;   // SIGMA = 1
                }
            }
        }
    }

#pragma unroll
    for (int off = 16; off; off >>= 1) acc1 += __shfl_down_sync(0xffffffffu, acc1, off);

    __shared__ float sw[8];
    __shared__ bool s_last;
    if (lane == 0) sw[warp] = acc1;
    __syncthreads();
    if (tid == 0) {
        float bs = 0.0f;
#pragma unroll
        for (int k = 0; k < 8; k++) bs += sw[k];
        g_bpart[blockIdx.x] = bs;
        __threadfence();
        s_last = (atomicAdd(&g_done, 1u) == (unsigned)(gridDim.x - 1));
    }
    __syncthreads();

    if (s_last) {
        __shared__ double dred[256];
        double s = (double)g_bpart[tid] + (double)g_bpart[tid + 256];
        s += 0.1 * ((double)g_apart[tid] + (double)g_apart[tid + 256] +
                    (double)g_apart[tid + 512]);        // E_THETA = 0.1
        dred[tid] = s;
        __syncthreads();
        for (int st = 128; st; st >>= 1) {
            if (tid < st) dred[tid] += dred[tid + st];
            __syncthreads();
        }
        if (tid == 0) {
            out[0] = (float)(dred[0] / (double)BB);      // E_ALPHA = 1
            g_any = 0u;                                  // all blocks already read it
            g_done = 0u;                                 // reset for graph replay
        }
    }
}

// ---------------------------------------------------------------------------
extern "C" void kernel_launch(void* const* d_in, const int* in_sizes, int n_in,
                              void* d_out, int out_size) {
    (void)in_sizes; (void)n_in; (void)out_size;
    const float* a  = (const float*)d_in[0];   // actioness   [4096,750]
    const float* a2 = (const float*)d_in[1];   // actioness_2 [4096,750]
    float* out = (float*)d_out;

    k_ns_part<<<A_GRID, 256>>>(a, a2);
    k_reduce_mask<<<21, 512>>>();
    k_main<<<MAIN_GRID, 256>>>(a, a2, out);
}